// round 5
// baseline (speedup 1.0000x reference)
#include <cuda_runtime.h>

// Problem constants (fixed by setup_inputs: x,y = [8,3,512,512] fp32)
#define HH 512
#define WW 512
#define NC 24              // 8*3 planes
#define TILE_W 32
#define TILE_H 64
#define HALO 5
#define ROWS_H (TILE_H + 2 * HALO)   // 74 hpass rows
#define SW 36                        // padded smem row stride (floats)
#define TPX 16             // col tiles (512/32)
#define TPY 8              // row tiles (512/64)
#define NBLK (NC * TPX * TPY)        // 3072
#define NTHREADS 256
#define PLANE_H (ROWS_H * SW)        // 2664 floats per hpass plane

#define C3 1e-4f
#define EPSV 1e-12f

__device__ float g_partials[NBLK];
__device__ int   g_counter;      // zero-initialized; self-resets each call

// Gaussian(sigma=1.5, K=11), normalized — matches reference to ~1e-7
#define W0 0.00102838f
#define W1 0.00759876f
#define W2 0.03600077f
#define W3 0.10936079f
#define W4 0.21300554f
#define W5 0.26601172f

typedef unsigned long long ull;

__device__ __forceinline__ ull pack2(float lo, float hi) {
    ull r; asm("mov.b64 %0, {%1, %2};" : "=l"(r) : "f"(lo), "f"(hi)); return r;
}
__device__ __forceinline__ void unpack2(ull v, float& lo, float& hi) {
    asm("mov.b64 {%0, %1}, %2;" : "=f"(lo), "=f"(hi) : "l"(v));
}
__device__ __forceinline__ ull fma2(ull a, ull b, ull c) {
    ull d; asm("fma.rn.f32x2 %0, %1, %2, %3;" : "=l"(d) : "l"(a), "l"(b), "l"(c)); return d;
}
__device__ __forceinline__ ull mul2(ull a, ull b) {
    ull d; asm("mul.rn.f32x2 %0, %1, %2;" : "=l"(d) : "l"(a), "l"(b)); return d;
}
// shifted pair: (hi(a), lo(b))
__device__ __forceinline__ ull shp(ull a, ull b) {
    float alo, ahi, blo, bhi;
    unpack2(a, alo, ahi); unpack2(b, blo, bhi);
    return pack2(ahi, blo);
}
__device__ __forceinline__ ull getpair(const ull* A, int s) {
    return (s & 1) ? shp(A[s >> 1], A[(s >> 1) + 1]) : A[s >> 1];
}

#define DECL_W2(name) \
    const ull name[11] = { pack2(W0,W0), pack2(W1,W1), pack2(W2,W2), pack2(W3,W3), \
                           pack2(W4,W4), pack2(W5,W5), pack2(W4,W4), pack2(W3,W3), \
                           pack2(W2,W2), pack2(W1,W1), pack2(W0,W0) }

// conv of data pairs + conv of squared pairs (for mu_* and E[**]) over 8 outputs
__device__ __forceinline__ void conv_sq(const ull* A, const ull* W, ull mu[4], ull sq[4]) {
    #pragma unroll
    for (int m = 0; m < 4; m++) { mu[m] = 0ull; sq[m] = 0ull; }
    #pragma unroll
    for (int s = 3; s <= 19; s++) {
        const ull p  = getpair(A, s);
        const ull p2 = mul2(p, p);
        #pragma unroll
        for (int m = 0; m < 4; m++) {
            const int k = s - 3 - 2 * m;
            if (k >= 0 && k <= 10) {
                mu[m] = fma2(p,  W[k], mu[m]);
                sq[m] = fma2(p2, W[k], sq[m]);
            }
        }
    }
}

// conv of elementwise product pairs (for E[xy]) over 8 outputs
__device__ __forceinline__ void conv_xy(const ull* A, const ull* B, const ull* W, ull acc[4]) {
    #pragma unroll
    for (int m = 0; m < 4; m++) acc[m] = 0ull;
    #pragma unroll
    for (int s = 3; s <= 19; s++) {
        const ull t = mul2(getpair(A, s), getpair(B, s));
        #pragma unroll
        for (int m = 0; m < 4; m++) {
            const int k = s - 3 - 2 * m;
            if (k >= 0 && k <= 10) acc[m] = fma2(t, W[k], acc[m]);
        }
    }
}

// store 8 packed outputs (4 ull = 32B) with r-parity swizzle for bank spread
__device__ __forceinline__ void store8(float* dst, const ull a[4], int swap) {
    ulonglong2 lo, hi;
    lo.x = a[0]; lo.y = a[1]; hi.x = a[2]; hi.y = a[3];
    ulonglong2* d = (ulonglong2*)dst;
    if (swap) { d[1] = hi; d[0] = lo; }
    else      { d[0] = lo; d[1] = hi; }
}

template <bool INTERIOR>
__device__ __forceinline__ void hgroup(const float* __restrict__ xp,
                                       const float* __restrict__ yp,
                                       float* __restrict__ s_h,
                                       int row0, int col0, int i)
{
    const int r = i >> 2, g = i & 3;
    const int gr  = row0 + r - HALO;
    const int gc0 = col0 + 8 * g - 8;

    DECL_W2(Wp);

    ull A[12], B[12];
    #pragma unroll
    for (int q = 0; q < 6; q++) {
        const int gc = gc0 + 4 * q;
        ulonglong2 va, vb;
        if (INTERIOR || ((unsigned)gr < HH && (unsigned)gc < (WW - 3))) {
            va = *(const ulonglong2*)(xp + gr * WW + gc);
            vb = *(const ulonglong2*)(yp + gr * WW + gc);
        } else {
            va.x = va.y = 0ull; vb.x = vb.y = 0ull;
        }
        A[2*q] = va.x; A[2*q+1] = va.y;
        B[2*q] = vb.x; B[2*q+1] = vb.y;
    }

    float* dst = s_h + r * SW + 8 * g;
    const int swap = r & 1;
    ull mu[4], sq[4];

    conv_sq(A, Wp, mu, sq);                 // mu_x, E[xx]
    store8(dst + 0 * PLANE_H, mu, swap);
    store8(dst + 3 * PLANE_H, sq, swap);

    conv_xy(A, B, Wp, mu);                  // E[xy]   (A and B both live here)
    store8(dst + 2 * PLANE_H, mu, swap);

    conv_sq(B, Wp, mu, sq);                 // mu_y, E[yy]
    store8(dst + 1 * PLANE_H, mu, swap);
    store8(dst + 4 * PLANE_H, sq, swap);
}

// Streaming vertical 11-tap conv over a column pair: 4 output rows, f32x2 packed.
__device__ __forceinline__ void vconv4(const float* __restrict__ colp,
                                       const ull w2[11], ull acc[4])
{
    acc[0] = acc[1] = acc[2] = acc[3] = 0ull;
    #pragma unroll
    for (int k = 0; k < 14; k++) {
        const ull v = *(const ull*)(colp + k * SW);
        #pragma unroll
        for (int r = 0; r < 4; r++) {
            const int j = k - r;
            if (j >= 0 && j <= 10) acc[r] = fma2(v, w2[j], acc[r]);
        }
    }
}

__global__ __launch_bounds__(NTHREADS, 4) void ssim_structure_kernel(
    const float* __restrict__ x, const float* __restrict__ y, float* __restrict__ out)
{
    extern __shared__ float s_h[];          // 5 * PLANE_H = 53280 B
    __shared__ float warpsum[8];
    __shared__ bool  is_last;

    const int tid  = threadIdx.x;
    const int row0 = blockIdx.y * TILE_H;
    const int col0 = blockIdx.x * TILE_W;
    const float* xp = x + (size_t)blockIdx.z * (HH * WW);
    const float* yp = y + (size_t)blockIdx.z * (HH * WW);

    const bool interior = (row0 >= HALO) && (row0 + ROWS_H - HALO <= HH) &&
                          (col0 >= 8)    && (col0 + TILE_W + 16 <= WW);

    // ---- horizontal pass: 74 rows x 4 groups of 8 outputs = 296 items ----
    if (interior) {
        hgroup<true>(xp, yp, s_h, row0, col0, tid);
        if (tid + NTHREADS < ROWS_H * 4)
            hgroup<true>(xp, yp, s_h, row0, col0, tid + NTHREADS);
    } else {
        hgroup<false>(xp, yp, s_h, row0, col0, tid);
        if (tid + NTHREADS < ROWS_H * 4)
            hgroup<false>(xp, yp, s_h, row0, col0, tid + NTHREADS);
    }
    __syncthreads();

    // ---- vertical pass: thread = 2 cols x 4 rows; planes streamed ----
    float lsum = 0.0f;
    {
        const int cp = tid & 15;             // column pair (cols 2cp, 2cp+1)
        const int r0 = (tid >> 4) * 4;       // output rows r0..r0+3
        DECL_W2(w2);
        const float* base = s_h + r0 * SW + 2 * cp;
        ull acc[4];

        float mx[4][2], my[4][2], sxy[4][2], sx[4][2], sy[4][2];

        vconv4(base + 0 * PLANE_H, w2, acc);                     // mu_x
        #pragma unroll
        for (int r = 0; r < 4; r++) unpack2(acc[r], mx[r][0], mx[r][1]);

        vconv4(base + 1 * PLANE_H, w2, acc);                     // mu_y
        #pragma unroll
        for (int r = 0; r < 4; r++) unpack2(acc[r], my[r][0], my[r][1]);

        vconv4(base + 2 * PLANE_H, w2, acc);                     // E[xy]
        #pragma unroll
        for (int r = 0; r < 4; r++) {
            float e0, e1; unpack2(acc[r], e0, e1);
            sxy[r][0] = e0 - mx[r][0] * my[r][0];
            sxy[r][1] = e1 - mx[r][1] * my[r][1];
        }

        vconv4(base + 3 * PLANE_H, w2, acc);                     // E[xx]
        #pragma unroll
        for (int r = 0; r < 4; r++) {
            float e0, e1; unpack2(acc[r], e0, e1);
            sx[r][0] = fmaxf(e0 - mx[r][0] * mx[r][0], EPSV);
            sx[r][1] = fmaxf(e1 - mx[r][1] * mx[r][1], EPSV);
        }

        vconv4(base + 4 * PLANE_H, w2, acc);                     // E[yy]
        #pragma unroll
        for (int r = 0; r < 4; r++) {
            float e0, e1; unpack2(acc[r], e0, e1);
            sy[r][0] = fmaxf(e0 - my[r][0] * my[r][0], EPSV);
            sy[r][1] = fmaxf(e1 - my[r][1] * my[r][1], EPSV);
        }

        #pragma unroll
        for (int r = 0; r < 4; r++) {
            #pragma unroll
            for (int j = 0; j < 2; j++) {
                lsum += __fdividef(sxy[r][j] + C3,
                                   sqrtf(sx[r][j] * sy[r][j]) + C3);
            }
        }
    }

    // ---- block reduction -> partial ----
    #pragma unroll
    for (int o = 16; o; o >>= 1)
        lsum += __shfl_down_sync(0xffffffffu, lsum, o);
    if ((tid & 31) == 0) warpsum[tid >> 5] = lsum;
    __syncthreads();
    if (tid == 0) {
        float v = 0.0f;
        #pragma unroll
        for (int w = 0; w < 8; w++) v += warpsum[w];
        const int bid = (blockIdx.z * TPY + blockIdx.y) * TPX + blockIdx.x;
        g_partials[bid] = v;
        __threadfence();
        const int done = atomicAdd(&g_counter, 1);
        is_last = (done == NBLK - 1);
    }
    __syncthreads();

    // ---- last block: deterministic final reduction ----
    if (is_last) {
        float s = 0.0f;
        for (int i = tid; i < NBLK; i += NTHREADS) s += g_partials[i];
        #pragma unroll
        for (int o = 16; o; o >>= 1)
            s += __shfl_down_sync(0xffffffffu, s, o);
        if ((tid & 31) == 0) warpsum[tid >> 5] = s;
        __syncthreads();
        if (tid == 0) {
            float v = 0.0f;
            #pragma unroll
            for (int w = 0; w < 8; w++) v += warpsum[w];
            const float denom = 1.0f / ((float)NC * (float)HH * (float)WW);
            out[0] = 1.0f - v * denom;
            g_counter = 0;   // self-reset for the next (graph-replayed) call
        }
    }
}

extern "C" void kernel_launch(void* const* d_in, const int* in_sizes, int n_in,
                              void* d_out, int out_size)
{
    (void)in_sizes; (void)n_in; (void)out_size;
    const float* x = (const float*)d_in[0];
    const float* y = (const float*)d_in[1];
    float* out = (float*)d_out;

    const int smem_bytes = 5 * PLANE_H * (int)sizeof(float);   // 53280
    cudaFuncSetAttribute(ssim_structure_kernel,
                         cudaFuncAttributeMaxDynamicSharedMemorySize, smem_bytes);

    dim3 grid(TPX, TPY, NC);
    ssim_structure_kernel<<<grid, NTHREADS, smem_bytes>>>(x, y, out);
}

// round 6
// speedup vs baseline: 1.0977x; 1.0977x over previous
#include <cuda_runtime.h>

// Problem constants (fixed by setup_inputs: x,y = [8,3,512,512] fp32)
#define HH 512
#define WW 512
#define NC 24              // 8*3 planes
#define TILE_W 32
#define TILE_H 64
#define HALO 5
#define ROWS_H (TILE_H + 2 * HALO)   // 74 hpass rows
#define SW 36                        // padded smem row stride (floats)
#define TPX 16             // col tiles (512/32)
#define TPY 8              // row tiles (512/64)
#define NBLK (NC * TPX * TPY)        // 3072
#define NTHREADS 256
#define PLANE_H (ROWS_H * SW)        // 2664 floats per hpass plane

#define C3 1e-4f
#define EPSV 1e-12f

__device__ float g_partials[NBLK];
__device__ int   g_counter;      // zero-initialized; self-resets each call

// Gaussian(sigma=1.5, K=11), normalized — matches reference to ~1e-7
#define W0 0.00102838f
#define W1 0.00759876f
#define W2 0.03600077f
#define W3 0.10936079f
#define W4 0.21300554f
#define W5 0.26601172f

typedef unsigned long long ull;

__device__ __forceinline__ ull pack2(float lo, float hi) {
    ull r; asm("mov.b64 %0, {%1, %2};" : "=l"(r) : "f"(lo), "f"(hi)); return r;
}
__device__ __forceinline__ void unpack2(ull v, float& lo, float& hi) {
    asm("mov.b64 {%0, %1}, %2;" : "=f"(lo), "=f"(hi) : "l"(v));
}
__device__ __forceinline__ ull fma2(ull a, ull b, ull c) {
    ull d; asm("fma.rn.f32x2 %0, %1, %2, %3;" : "=l"(d) : "l"(a), "l"(b), "l"(c)); return d;
}

// ---- scalar 11-tap convs over an 8-output group; window v[24], outputs j=0..7
// output j consumes v[j+3 .. j+13]
__device__ __forceinline__ void conv8(const float* v, float acc[8]) {
    const float wgt[11] = {W0, W1, W2, W3, W4, W5, W4, W3, W2, W1, W0};
    #pragma unroll
    for (int j = 0; j < 8; j++) acc[j] = 0.0f;
    #pragma unroll
    for (int k = 0; k < 11; k++) {
        const float w = wgt[k];
        #pragma unroll
        for (int j = 0; j < 8; j++)
            acc[j] = fmaf(v[j + 3 + k], w, acc[j]);
    }
}
// conv of v*v (one transient FMUL per window position)
__device__ __forceinline__ void conv8_sq(const float* v, float acc[8]) {
    const float wgt[11] = {W0, W1, W2, W3, W4, W5, W4, W3, W2, W1, W0};
    #pragma unroll
    for (int j = 0; j < 8; j++) acc[j] = 0.0f;
    #pragma unroll
    for (int s = 3; s <= 20; s++) {
        const float p2 = v[s] * v[s];
        #pragma unroll
        for (int j = 0; j < 8; j++) {
            const int k = s - 3 - j;
            if (k >= 0 && k <= 10) acc[j] = fmaf(p2, wgt[k], acc[j]);
        }
    }
}
// conv of a*b
__device__ __forceinline__ void conv8_xy(const float* a, const float* b, float acc[8]) {
    const float wgt[11] = {W0, W1, W2, W3, W4, W5, W4, W3, W2, W1, W0};
    #pragma unroll
    for (int j = 0; j < 8; j++) acc[j] = 0.0f;
    #pragma unroll
    for (int s = 3; s <= 20; s++) {
        const float t = a[s] * b[s];
        #pragma unroll
        for (int j = 0; j < 8; j++) {
            const int k = s - 3 - j;
            if (k >= 0 && k <= 10) acc[j] = fmaf(t, wgt[k], acc[j]);
        }
    }
}

__device__ __forceinline__ void store8(float* dst, const float acc[8]) {
    *(float4*)(dst + 0) = make_float4(acc[0], acc[1], acc[2], acc[3]);
    *(float4*)(dst + 4) = make_float4(acc[4], acc[5], acc[6], acc[7]);
}

template <bool INTERIOR>
__device__ __forceinline__ void load24(const float* __restrict__ p, int gr, int gc0,
                                       float v[24])
{
    #pragma unroll
    for (int q = 0; q < 6; q++) {
        const int gc = gc0 + 4 * q;
        float4 f;
        if (INTERIOR || ((unsigned)gr < HH && (unsigned)gc < WW)) {
            f = *(const float4*)(p + gr * WW + gc);
        } else {
            f = make_float4(0.f, 0.f, 0.f, 0.f);
        }
        v[4*q+0] = f.x; v[4*q+1] = f.y; v[4*q+2] = f.z; v[4*q+3] = f.w;
    }
}

template <bool INTERIOR>
__device__ __forceinline__ void hgroup(const float* __restrict__ xp,
                                       const float* __restrict__ yp,
                                       float* __restrict__ s_h,
                                       int row0, int col0, int i)
{
    const int r = i >> 2, g = i & 3;
    const int gr  = row0 + r - HALO;
    const int gc0 = col0 + 8 * g - 8;      // window covers output cols 8g..8g+7
    float* dst = s_h + r * SW + 8 * g;
    float acc[8];

    float A[24];
    load24<INTERIOR>(xp, gr, gc0, A);
    conv8(A, acc);    store8(dst + 0 * PLANE_H, acc);   // mu_x
    conv8_sq(A, acc); store8(dst + 3 * PLANE_H, acc);   // E[xx]

    float B[24];
    load24<INTERIOR>(yp, gr, gc0, B);
    conv8_xy(A, B, acc); store8(dst + 2 * PLANE_H, acc); // E[xy]
    conv8(B, acc);    store8(dst + 1 * PLANE_H, acc);   // mu_y
    conv8_sq(B, acc); store8(dst + 4 * PLANE_H, acc);   // E[yy]
}

// Streaming vertical 11-tap conv over a column pair: 4 output rows, f32x2 packed.
__device__ __forceinline__ void vconv4(const float* __restrict__ colp,
                                       const ull w2[11], ull acc[4])
{
    acc[0] = acc[1] = acc[2] = acc[3] = 0ull;
    #pragma unroll
    for (int k = 0; k < 14; k++) {
        const ull v = *(const ull*)(colp + k * SW);
        #pragma unroll
        for (int r = 0; r < 4; r++) {
            const int j = k - r;
            if (j >= 0 && j <= 10) acc[r] = fma2(v, w2[j], acc[r]);
        }
    }
}

#define DECL_W2(name) \
    const ull name[11] = { pack2(W0,W0), pack2(W1,W1), pack2(W2,W2), pack2(W3,W3), \
                           pack2(W4,W4), pack2(W5,W5), pack2(W4,W4), pack2(W3,W3), \
                           pack2(W2,W2), pack2(W1,W1), pack2(W0,W0) }

__global__ __launch_bounds__(NTHREADS, 4) void ssim_structure_kernel(
    const float* __restrict__ x, const float* __restrict__ y, float* __restrict__ out)
{
    extern __shared__ float s_h[];          // 5 * PLANE_H = 53280 B
    __shared__ float warpsum[8];
    __shared__ bool  is_last;

    const int tid  = threadIdx.x;
    const int row0 = blockIdx.y * TILE_H;
    const int col0 = blockIdx.x * TILE_W;
    const float* xp = x + (size_t)blockIdx.z * (HH * WW);
    const float* yp = y + (size_t)blockIdx.z * (HH * WW);

    const bool interior = (row0 >= HALO) && (row0 + ROWS_H - HALO <= HH) &&
                          (col0 >= 8)    && (col0 + TILE_W + 16 <= WW);

    // ---- horizontal pass: 74 rows x 4 groups of 8 outputs = 296 items ----
    if (interior) {
        hgroup<true>(xp, yp, s_h, row0, col0, tid);
        if (tid + NTHREADS < ROWS_H * 4)
            hgroup<true>(xp, yp, s_h, row0, col0, tid + NTHREADS);
    } else {
        hgroup<false>(xp, yp, s_h, row0, col0, tid);
        if (tid + NTHREADS < ROWS_H * 4)
            hgroup<false>(xp, yp, s_h, row0, col0, tid + NTHREADS);
    }
    __syncthreads();

    // ---- vertical pass: thread = 2 cols x 4 rows; planes streamed, f32x2 ----
    float lsum = 0.0f;
    {
        const int cp = tid & 15;             // column pair (cols 2cp, 2cp+1)
        const int r0 = (tid >> 4) * 4;       // output rows r0..r0+3
        DECL_W2(w2);
        const float* base = s_h + r0 * SW + 2 * cp;
        ull acc[4];

        float mx[4][2], my[4][2], sxy[4][2], sx[4][2], sy[4][2];

        vconv4(base + 0 * PLANE_H, w2, acc);                     // mu_x
        #pragma unroll
        for (int r = 0; r < 4; r++) unpack2(acc[r], mx[r][0], mx[r][1]);

        vconv4(base + 1 * PLANE_H, w2, acc);                     // mu_y
        #pragma unroll
        for (int r = 0; r < 4; r++) unpack2(acc[r], my[r][0], my[r][1]);

        vconv4(base + 2 * PLANE_H, w2, acc);                     // E[xy]
        #pragma unroll
        for (int r = 0; r < 4; r++) {
            float e0, e1; unpack2(acc[r], e0, e1);
            sxy[r][0] = e0 - mx[r][0] * my[r][0];
            sxy[r][1] = e1 - mx[r][1] * my[r][1];
        }

        vconv4(base + 3 * PLANE_H, w2, acc);                     // E[xx]
        #pragma unroll
        for (int r = 0; r < 4; r++) {
            float e0, e1; unpack2(acc[r], e0, e1);
            sx[r][0] = fmaxf(e0 - mx[r][0] * mx[r][0], EPSV);
            sx[r][1] = fmaxf(e1 - mx[r][1] * mx[r][1], EPSV);
        }

        vconv4(base + 4 * PLANE_H, w2, acc);                     // E[yy]
        #pragma unroll
        for (int r = 0; r < 4; r++) {
            float e0, e1; unpack2(acc[r], e0, e1);
            sy[r][0] = fmaxf(e0 - my[r][0] * my[r][0], EPSV);
            sy[r][1] = fmaxf(e1 - my[r][1] * my[r][1], EPSV);
        }

        #pragma unroll
        for (int r = 0; r < 4; r++) {
            #pragma unroll
            for (int j = 0; j < 2; j++) {
                lsum += __fdividef(sxy[r][j] + C3,
                                   sqrtf(sx[r][j] * sy[r][j]) + C3);
            }
        }
    }

    // ---- block reduction -> partial ----
    #pragma unroll
    for (int o = 16; o; o >>= 1)
        lsum += __shfl_down_sync(0xffffffffu, lsum, o);
    if ((tid & 31) == 0) warpsum[tid >> 5] = lsum;
    __syncthreads();
    if (tid == 0) {
        float v = 0.0f;
        #pragma unroll
        for (int w = 0; w < 8; w++) v += warpsum[w];
        const int bid = (blockIdx.z * TPY + blockIdx.y) * TPX + blockIdx.x;
        g_partials[bid] = v;
        __threadfence();
        const int done = atomicAdd(&g_counter, 1);
        is_last = (done == NBLK - 1);
    }
    __syncthreads();

    // ---- last block: deterministic final reduction ----
    if (is_last) {
        float s = 0.0f;
        for (int i = tid; i < NBLK; i += NTHREADS) s += g_partials[i];
        #pragma unroll
        for (int o = 16; o; o >>= 1)
            s += __shfl_down_sync(0xffffffffu, s, o);
        if ((tid & 31) == 0) warpsum[tid >> 5] = s;
        __syncthreads();
        if (tid == 0) {
            float v = 0.0f;
            #pragma unroll
            for (int w = 0; w < 8; w++) v += warpsum[w];
            const float denom = 1.0f / ((float)NC * (float)HH * (float)WW);
            out[0] = 1.0f - v * denom;
            g_counter = 0;   // self-reset for the next (graph-replayed) call
        }
    }
}

extern "C" void kernel_launch(void* const* d_in, const int* in_sizes, int n_in,
                              void* d_out, int out_size)
{
    (void)in_sizes; (void)n_in; (void)out_size;
    const float* x = (const float*)d_in[0];
    const float* y = (const float*)d_in[1];
    float* out = (float*)d_out;

    const int smem_bytes = 5 * PLANE_H * (int)sizeof(float);   // 53280
    cudaFuncSetAttribute(ssim_structure_kernel,
                         cudaFuncAttributeMaxDynamicSharedMemorySize, smem_bytes);

    dim3 grid(TPX, TPY, NC);
    ssim_structure_kernel<<<grid, NTHREADS, smem_bytes>>>(x, y, out);
}